// round 16
// baseline (speedup 1.0000x reference)
#include <cuda_runtime.h>
#include <cuda_bf16.h>

// ---------------------------------------------------------------------------
// GCN 2-layer forward. CSR aggregation + pipelined mma.sync bf16-split GEMM1.
//   h1 = x @ W1                    [N,128]  (HMMA m16n8k16, 3-way bf16 split,
//                                           double-buffered cp.async pipeline)
//   hid = relu(A @ h1 + b1)        (registers/smem only)
//   h2 = hid @ W2                  [N,16]   (fused into gather1)
//   out = log_softmax(A @ h2 + b2) [N,16]
// edge_index is int32 (JAX x64-disabled truncates the requested int64).
// CSR build forked onto a side stream, overlapped with GEMM1.
// ---------------------------------------------------------------------------

#define NMAX 50000
#define EMAX 800000
typedef unsigned long long ull;

__device__ int   g_indeg [NMAX];
__device__ int   g_cursor[NMAX];
__device__ int   g_rowptr[NMAX + 1];
__device__ int   g_scan  [NMAX];
__device__ int   g_bsum  [256];
__device__ int   g_boff  [256];
__device__ float g_dinv  [NMAX];
__device__ __align__(16) ull   g_emeta[EMAX];        // hi: norm bits, lo: src
__device__ __align__(16) float g_h1   [NMAX * 128];
__device__ __align__(16) float g_h2   [NMAX * 16];
__device__ __align__(16) __nv_bfloat16 g_W1h[256 * 128];
__device__ __align__(16) __nv_bfloat16 g_W1l[256 * 128];

// ---------------- helpers ---------------------------------------------------

__device__ __forceinline__ ull pack2f(float lo, float hi) {
    ull d;
    asm("mov.b64 %0, {%1, %2};" : "=l"(d) : "r"(__float_as_uint(lo)), "r"(__float_as_uint(hi)));
    return d;
}
__device__ __forceinline__ void ldm_x4(unsigned& r0, unsigned& r1, unsigned& r2, unsigned& r3,
                                       unsigned addr) {
    asm volatile("ldmatrix.sync.aligned.m8n8.x4.shared.b16 {%0,%1,%2,%3}, [%4];"
                 : "=r"(r0), "=r"(r1), "=r"(r2), "=r"(r3) : "r"(addr));
}
__device__ __forceinline__ void ldm_x4t(unsigned& r0, unsigned& r1, unsigned& r2, unsigned& r3,
                                        unsigned addr) {
    asm volatile("ldmatrix.sync.aligned.m8n8.x4.trans.shared.b16 {%0,%1,%2,%3}, [%4];"
                 : "=r"(r0), "=r"(r1), "=r"(r2), "=r"(r3) : "r"(addr));
}
__device__ __forceinline__ void mma_bf16(float* c, const unsigned* a, unsigned b0, unsigned b1) {
    asm volatile("mma.sync.aligned.m16n8k16.row.col.f32.bf16.bf16.f32 "
                 "{%0,%1,%2,%3}, {%4,%5,%6,%7}, {%8,%9}, {%0,%1,%2,%3};"
                 : "+f"(c[0]), "+f"(c[1]), "+f"(c[2]), "+f"(c[3])
                 : "r"(a[0]), "r"(a[1]), "r"(a[2]), "r"(a[3]), "r"(b0), "r"(b1));
}
__device__ __forceinline__ void cpa16(unsigned dst, const void* src) {
    asm volatile("cp.async.ca.shared.global [%0], [%1], 16;" :: "r"(dst), "l"(src));
}
__device__ __forceinline__ void split_pack(const float* xs, ull& hp, ull& lp) {
    unsigned hw0, hw1, lw0, lw1;
    __nv_bfloat16 h0 = __float2bfloat16(xs[0]);
    __nv_bfloat16 h1 = __float2bfloat16(xs[1]);
    __nv_bfloat16 l0 = __float2bfloat16(xs[0] - __bfloat162float(h0));
    __nv_bfloat16 l1 = __float2bfloat16(xs[1] - __bfloat162float(h1));
    hw0 = (unsigned)__bfloat16_as_ushort(h0) | ((unsigned)__bfloat16_as_ushort(h1) << 16);
    lw0 = (unsigned)__bfloat16_as_ushort(l0) | ((unsigned)__bfloat16_as_ushort(l1) << 16);
    __nv_bfloat16 h2 = __float2bfloat16(xs[2]);
    __nv_bfloat16 h3 = __float2bfloat16(xs[3]);
    __nv_bfloat16 l2 = __float2bfloat16(xs[2] - __bfloat162float(h2));
    __nv_bfloat16 l3 = __float2bfloat16(xs[3] - __bfloat162float(h3));
    hw1 = (unsigned)__bfloat16_as_ushort(h2) | ((unsigned)__bfloat16_as_ushort(h3) << 16);
    lw1 = (unsigned)__bfloat16_as_ushort(l2) | ((unsigned)__bfloat16_as_ushort(l3) << 16);
    hp = ((ull)hw1 << 32) | hw0;
    lp = ((ull)lw1 << 32) | lw0;
}

// ---------------- CSR build ------------------------------------------------

__global__ void k_init(int n) {
    int i = blockIdx.x * blockDim.x + threadIdx.x;
    if (i < n) { g_indeg[i] = 0; g_cursor[i] = 0; }
}

__global__ void k_deg_count(const int* __restrict__ dst, int E) {
    int e = blockIdx.x * blockDim.x + threadIdx.x;
    if (e < E) atomicAdd(&g_indeg[dst[e]], 1);
}

__global__ void k_scan1(int n) {
    __shared__ int wsum[8];
    int t = threadIdx.x, i = blockIdx.x * 256 + t;
    int lane = t & 31, w = t >> 5;
    int x = (i < n) ? g_indeg[i] : 0;
#pragma unroll
    for (int o = 1; o < 32; o <<= 1) {
        int y = __shfl_up_sync(0xffffffffu, x, o);
        if (lane >= o) x += y;
    }
    if (lane == 31) wsum[w] = x;
    __syncthreads();
    if (w == 0) {
        int s = (lane < 8) ? wsum[lane] : 0;
#pragma unroll
        for (int o = 1; o < 8; o <<= 1) {
            int y = __shfl_up_sync(0xffffffffu, s, o);
            if (lane >= o) s += y;
        }
        if (lane < 8) wsum[lane] = s;
    }
    __syncthreads();
    if (w > 0) x += wsum[w - 1];
    if (i < n) g_scan[i] = x;
    if (t == 255) g_bsum[blockIdx.x] = x;
}

__global__ void k_scan2(int nb) {
    __shared__ int wsum[8];
    int t = threadIdx.x;
    int lane = t & 31, w = t >> 5;
    int v = (t < nb) ? g_bsum[t] : 0;
    int x = v;
#pragma unroll
    for (int o = 1; o < 32; o <<= 1) {
        int y = __shfl_up_sync(0xffffffffu, x, o);
        if (lane >= o) x += y;
    }
    if (lane == 31) wsum[w] = x;
    __syncthreads();
    if (w == 0) {
        int s = (lane < 8) ? wsum[lane] : 0;
#pragma unroll
        for (int o = 1; o < 8; o <<= 1) {
            int y = __shfl_up_sync(0xffffffffu, s, o);
            if (lane >= o) s += y;
        }
        if (lane < 8) wsum[lane] = s;
    }
    __syncthreads();
    if (w > 0) x += wsum[w - 1];
    g_boff[t] = x - v;   // exclusive
}

__global__ void k_scan3(int n) {     // rowptr + dinv
    int i = blockIdx.x * blockDim.x + threadIdx.x;
    if (i >= n) return;
    int deg = g_indeg[i];
    int off = g_boff[i >> 8];
    g_rowptr[i] = g_scan[i] - deg + off;
    if (i == n - 1) g_rowptr[n] = g_scan[i] + off;
    g_dinv[i] = rsqrtf((float)(deg + 1));
}

__global__ void k_fill(const int* __restrict__ src, const int* __restrict__ dst, int E) {
    int e = blockIdx.x * blockDim.x + threadIdx.x;
    if (e >= E) return;
    int s = src[e], d = dst[e];
    int pos = g_rowptr[d] + atomicAdd(&g_cursor[d], 1);
    float nm = g_dinv[s] * g_dinv[d];
    g_emeta[pos] = ((ull)__float_as_uint(nm) << 32) | (unsigned)s;
}

// ---------------- W1 bf16 hi/lo pre-split ----------------------------------

__global__ void k_convW(const float* __restrict__ W) {
    int i = blockIdx.x * blockDim.x + threadIdx.x;
    if (i >= 256 * 128) return;
    float w = W[i];
    __nv_bfloat16 h = __float2bfloat16(w);
    g_W1h[i] = h;
    g_W1l[i] = __float2bfloat16(w - __bfloat162float(h));
}

// ---------------- GEMM1: pipelined mma.sync --------------------------------
// 128x128 tile, 8 warps (4m x 2n), K-chunks of 32, double-buffered:
//   stage(ch+1) overlapped with mma(ch). B staged via cp.async from the
//   pre-split g_W1h/g_W1l; A (X) LDG->regs before mma, convert+STS after.

#define A_PITCH 40
#define B_PITCH 136
#define A_SZ (128 * A_PITCH)
#define B_SZ (32 * B_PITCH)
#define G1_SMEM ((4 * A_SZ + 4 * B_SZ) * 2)   // bytes: 2 bufs x (Ah,Al,Bh,Bl)

__global__ void __launch_bounds__(256, 2) k_gemm1(const float* __restrict__ X, int n) {
    extern __shared__ __align__(16) __nv_bfloat16 dyn[];
    __nv_bfloat16* Ah[2] = {dyn,               dyn + A_SZ};
    __nv_bfloat16* Al[2] = {dyn + 2*A_SZ,      dyn + 3*A_SZ};
    __nv_bfloat16* Bh[2] = {dyn + 4*A_SZ,            dyn + 4*A_SZ + B_SZ};
    __nv_bfloat16* Bl[2] = {dyn + 4*A_SZ + 2*B_SZ,   dyn + 4*A_SZ + 3*B_SZ};

    const int tid  = threadIdx.x;
    const int wid  = tid >> 5;
    const int lane = tid & 31;
    const int wm   = wid & 3;
    const int wn   = wid >> 2;
    const int row0 = blockIdx.x * 128;

    float acc[2][8][4];
#pragma unroll
    for (int mt = 0; mt < 2; mt++)
#pragma unroll
        for (int nt = 0; nt < 8; nt++)
#pragma unroll
            for (int q = 0; q < 4; q++) acc[mt][nt][q] = 0.f;

    float4 xr[4];

    // ---- staging lambdas (macros by hand) ----
    // B copy: 512 16B-slots per h/l buffer; thread does 2+2
#define STAGE_B(kc, buf)                                                        \
    {                                                                           \
        int k0b = (kc) << 5;                                                    \
        _Pragma("unroll")                                                       \
        for (int it = 0; it < 2; it++) {                                        \
            int s = tid + (it << 8);                                            \
            int kk = s >> 4, g = (s & 15) << 3;                                 \
            unsigned dh = (unsigned)__cvta_generic_to_shared(&Bh[buf][kk * B_PITCH + g]); \
            unsigned dl = (unsigned)__cvta_generic_to_shared(&Bl[buf][kk * B_PITCH + g]); \
            cpa16(dh, g_W1h + (k0b + kk) * 128 + g);                            \
            cpa16(dl, g_W1l + (k0b + kk) * 128 + g);                            \
        }                                                                       \
        asm volatile("cp.async.commit_group;");                                 \
    }
    // A LDG into regs
#define LOAD_A(kc)                                                              \
    {                                                                           \
        int k0a = (kc) << 5;                                                    \
        _Pragma("unroll")                                                       \
        for (int it = 0; it < 4; it++) {                                        \
            int s = tid + (it << 8);                                            \
            int r = s >> 3, f4 = (s & 7) << 2;                                  \
            int gr = row0 + r;                                                  \
            xr[it] = make_float4(0.f, 0.f, 0.f, 0.f);                           \
            if (gr < n) xr[it] = *(const float4*)(X + (size_t)gr * 256 + k0a + f4); \
        }                                                                       \
    }
    // A convert + STS
#define STORE_A(buf)                                                            \
    {                                                                           \
        _Pragma("unroll")                                                       \
        for (int it = 0; it < 4; it++) {                                        \
            int s = tid + (it << 8);                                            \
            int r = s >> 3, f4 = (s & 7) << 2;                                  \
            float xs[4] = {xr[it].x, xr[it].y, xr[it].z, xr[it].w};             \
            ull hp, lp;                                                         \
            split_pack(xs, hp, lp);                                             \
            *(ull*)&Ah[buf][r * A_PITCH + f4] = hp;                             \
            *(ull*)&Al[buf][r * A_PITCH + f4] = lp;                             \
        }                                                                       \
    }

    // prologue: stage chunk 0
    STAGE_B(0, 0);
    LOAD_A(0);
    STORE_A(0);
    asm volatile("cp.async.wait_group 0;");
    __syncthreads();

    for (int ch = 0; ch < 8; ch++) {
        const int cur = ch & 1, nxt = cur ^ 1;
        if (ch < 7) {
            STAGE_B(ch + 1, nxt);
            LOAD_A(ch + 1);
        }

        // ---- compute on cur ----
#pragma unroll
        for (int ks = 0; ks < 32; ks += 16) {
            unsigned aH[2][4], aL[2][4];
#pragma unroll
            for (int mt = 0; mt < 2; mt++) {
                int ar = wm * 32 + mt * 16 + (lane & 15);
                int ac = ks + ((lane >> 4) << 3);
                unsigned addrH = (unsigned)__cvta_generic_to_shared(&Ah[cur][ar * A_PITCH + ac]);
                unsigned addrL = (unsigned)__cvta_generic_to_shared(&Al[cur][ar * A_PITCH + ac]);
                ldm_x4(aH[mt][0], aH[mt][1], aH[mt][2], aH[mt][3], addrH);
                ldm_x4(aL[mt][0], aL[mt][1], aL[mt][2], aL[mt][3], addrL);
            }
#pragma unroll
            for (int ng = 0; ng < 4; ng++) {
                int nb0 = wn * 64 + ng * 16;
                int br = ks + (lane & 15);
                int bc = nb0 + ((lane >> 4) << 3);
                unsigned addrH = (unsigned)__cvta_generic_to_shared(&Bh[cur][br * B_PITCH + bc]);
                unsigned addrL = (unsigned)__cvta_generic_to_shared(&Bl[cur][br * B_PITCH + bc]);
                unsigned bh[4], bl[4];
                ldm_x4t(bh[0], bh[1], bh[2], bh[3], addrH);
                ldm_x4t(bl[0], bl[1], bl[2], bl[3], addrL);
#pragma unroll
                for (int mt = 0; mt < 2; mt++) {
#pragma unroll
                    for (int nt = 0; nt < 2; nt++) {
                        float* c = acc[mt][ng * 2 + nt];
                        mma_bf16(c, aH[mt], bh[nt * 2], bh[nt * 2 + 1]);
                        mma_bf16(c, aH[mt], bl[nt * 2], bl[nt * 2 + 1]);
                        mma_bf16(c, aL[mt], bh[nt * 2], bh[nt * 2 + 1]);
                    }
                }
            }
        }

        if (ch < 7) {
            STORE_A(nxt);
            asm volatile("cp.async.wait_group 0;");
        }
        __syncthreads();
    }

    // ---- epilogue ----
#pragma unroll
    for (int mt = 0; mt < 2; mt++) {
#pragma unroll
        for (int nt = 0; nt < 8; nt++) {
            int col = wn * 64 + nt * 8 + ((lane & 3) << 1);
            int r0  = row0 + wm * 32 + mt * 16 + (lane >> 2);
            if (r0 < n)
                *(ull*)(g_h1 + (size_t)r0 * 128 + col) = pack2f(acc[mt][nt][0], acc[mt][nt][1]);
            if (r0 + 8 < n)
                *(ull*)(g_h1 + (size_t)(r0 + 8) * 128 + col) = pack2f(acc[mt][nt][2], acc[mt][nt][3]);
        }
    }
#undef STAGE_B
#undef LOAD_A
#undef STORE_A
}

// ---------------- fused gather1 + GEMM2 (warp per node) --------------------

__global__ void __launch_bounds__(256) k_gather1_gemm2(const float* __restrict__ b1,
                                                       const float* __restrict__ W2,
                                                       int n) {
    __shared__ float W2s[16][132];
    __shared__ float hidS[8][128];
    const int tid  = threadIdx.x;
    const int w    = tid >> 5;
    const int lane = tid & 31;

#pragma unroll
    for (int i = tid; i < 2048; i += 256) {
        int k = i >> 4, j = i & 15;
        W2s[j][k] = W2[k * 16 + j];
    }
    __syncthreads();

    int node = blockIdx.x * 8 + w;
    if (node >= n) return;
    int c = lane << 2;

    float di  = g_dinv[node];
    float di2 = di * di;
    float4 h  = *(const float4*)(g_h1 + (size_t)node * 128 + c);
    float4 a;
    a.x = di2 * h.x; a.y = di2 * h.y; a.z = di2 * h.z; a.w = di2 * h.w;

    int beg = g_rowptr[node], end = g_rowptr[node + 1];
    if (beg < end) {
        ull m0 = g_emeta[beg];
        float4 v0 = *(const float4*)(g_h1 + (size_t)(unsigned)m0 * 128 + c);
        for (int e = beg + 1; e < end; e++) {
            ull m1 = g_emeta[e];
            float4 v1 = *(const float4*)(g_h1 + (size_t)(unsigned)m1 * 128 + c);
            float nm = __uint_as_float((unsigned)(m0 >> 32));
            a.x += nm * v0.x; a.y += nm * v0.y; a.z += nm * v0.z; a.w += nm * v0.w;
            m0 = m1; v0 = v1;
        }
        float nm = __uint_as_float((unsigned)(m0 >> 32));
        a.x += nm * v0.x; a.y += nm * v0.y; a.z += nm * v0.z; a.w += nm * v0.w;
    }
    float4 b = *(const float4*)(b1 + c);
    float4 o;
    o.x = fmaxf(a.x + b.x, 0.f);
    o.y = fmaxf(a.y + b.y, 0.f);
    o.z = fmaxf(a.z + b.z, 0.f);
    o.w = fmaxf(a.w + b.w, 0.f);

    *(float4*)&hidS[w][c] = o;
    __syncwarp();

    const int j  = lane & 15;
    const int k0 = (lane >> 4) << 6;
    float acc = 0.f;
#pragma unroll
    for (int kk = 0; kk < 64; kk += 4) {
        float4 hv = *(float4*)&hidS[w][k0 + kk];
        float4 wv = *(float4*)&W2s[j][k0 + kk];
        acc += hv.x * wv.x + hv.y * wv.y + hv.z * wv.z + hv.w * wv.w;
    }
    acc += __shfl_down_sync(0xffffffffu, acc, 16);
    if (lane < 16) g_h2[(size_t)node * 16 + j] = acc;
}

// ---------------- gather layer 2 + log_softmax (4 lanes per node) ----------

__global__ void __launch_bounds__(256) k_gather2(const float* __restrict__ b2,
                                                 float* __restrict__ out, int n) {
    int g    = blockIdx.x * 256 + threadIdx.x;
    int node = g >> 2, q = g & 3;
    if (node >= n) return;
    int c = q << 2;

    float di  = g_dinv[node];
    float di2 = di * di;
    float4 h  = *(const float4*)(g_h2 + (size_t)node * 16 + c);
    float4 a;
    a.x = di2 * h.x; a.y = di2 * h.y; a.z = di2 * h.z; a.w = di2 * h.w;

    int beg = g_rowptr[node], end = g_rowptr[node + 1];
    if (beg < end) {
        ull m0 = g_emeta[beg];
        float4 v0 = *(const float4*)(g_h2 + (size_t)(unsigned)m0 * 16 + c);
        for (int e = beg + 1; e < end; e++) {
            ull m1 = g_emeta[e];
            float4 v1 = *(const float4*)(g_h2 + (size_t)(unsigned)m1 * 16 + c);
            float nm = __uint_as_float((unsigned)(m0 >> 32));
            a.x += nm * v0.x; a.y += nm * v0.y; a.z += nm * v0.z; a.w += nm * v0.w;
            m0 = m1; v0 = v1;
        }
        float nm = __uint_as_float((unsigned)(m0 >> 32));
        a.x += nm * v0.x; a.y += nm * v0.y; a.z += nm * v0.z; a.w += nm * v0.w;
    }
    float4 b = *(const float4*)(b2 + c);
    a.x += b.x; a.y += b.y; a.z += b.z; a.w += b.w;

    float m4 = fmaxf(fmaxf(a.x, a.y), fmaxf(a.z, a.w));
    m4 = fmaxf(m4, __shfl_xor_sync(0xffffffffu, m4, 1, 4));
    m4 = fmaxf(m4, __shfl_xor_sync(0xffffffffu, m4, 2, 4));
    float s4 = expf(a.x - m4) + expf(a.y - m4) + expf(a.z - m4) + expf(a.w - m4);
    s4 += __shfl_xor_sync(0xffffffffu, s4, 1, 4);
    s4 += __shfl_xor_sync(0xffffffffu, s4, 2, 4);
    float lse = m4 + logf(s4);

    float4 o;
    o.x = a.x - lse; o.y = a.y - lse; o.z = a.z - lse; o.w = a.w - lse;
    *(float4*)(out + (size_t)node * 16 + c) = o;
}

// ---------------------------------------------------------------------------

extern "C" void kernel_launch(void* const* d_in, const int* in_sizes, int n_in,
                              void* d_out, int out_size) {
    const float* x  = (const float*)d_in[0];
    const int*   ei = (const int*)d_in[1];          // int32 (JAX truncation)
    const float* W1 = (const float*)d_in[2];
    const float* b1 = (const float*)d_in[3];
    const float* W2 = (const float*)d_in[4];
    const float* b2 = (const float*)d_in[5];
    float*       out = (float*)d_out;

    const int n = in_sizes[0] / 256;
    const int E = in_sizes[1] / 2;
    const int* src = ei;
    const int* dst = ei + E;
    const int nb = (n + 255) / 256;

    const int T = 256;
    dim3 b(T);

    static cudaStream_t sCsr = nullptr;
    static cudaEvent_t  eFork = nullptr, eJoin = nullptr;
    if (!sCsr) {
        cudaStreamCreateWithFlags(&sCsr, cudaStreamNonBlocking);
        cudaEventCreateWithFlags(&eFork, cudaEventDisableTiming);
        cudaEventCreateWithFlags(&eJoin, cudaEventDisableTiming);
        cudaFuncSetAttribute(k_gemm1, cudaFuncAttributeMaxDynamicSharedMemorySize, G1_SMEM);
    }

    // fork: CSR build on side stream, W-split + GEMM1 on main stream
    cudaEventRecord(eFork, 0);
    cudaStreamWaitEvent(sCsr, eFork, 0);

    k_convW    <<<128, b>>>(W1);                          // launch 1 (main)
    k_init     <<<(n + T - 1) / T, b, 0, sCsr>>>(n);      // launch 2
    k_deg_count<<<(E + T - 1) / T, b, 0, sCsr>>>(dst, E); // launch 3

    k_gemm1<<<(n + 127) / 128, b, G1_SMEM>>>(x, n);       // launch 4 (ncu window)

    k_scan1    <<<nb, b, 0, sCsr>>>(n);
    k_scan2    <<<1, b, 0, sCsr>>>(nb);
    k_scan3    <<<nb, b, 0, sCsr>>>(n);
    k_fill     <<<(E + T - 1) / T, b, 0, sCsr>>>(src, dst, E);
    cudaEventRecord(eJoin, sCsr);

    // join, then the dependent chain
    cudaStreamWaitEvent(0, eJoin, 0);
    k_gather1_gemm2<<<(n + 7) / 8, b>>>(b1, W2, n);
    k_gather2<<<(n * 4 + T - 1) / T, b>>>(b2, out, n);
}

// round 17
// speedup vs baseline: 1.4728x; 1.4728x over previous
#include <cuda_runtime.h>
#include <cuda_bf16.h>

// ---------------------------------------------------------------------------
// GCN 2-layer forward. CSR aggregation + mma.sync bf16-split GEMM1 (R15 base,
// W1 pre-split to bf16 hi/lo once instead of per-block).
//   h1 = x @ W1                    [N,128]  (HMMA m16n8k16, 3-way bf16 split)
//   hid = relu(A @ h1 + b1)        (registers/smem only)
//   h2 = hid @ W2                  [N,16]   (fused into gather1)
//   out = log_softmax(A @ h2 + b2) [N,16]
// edge_index is int32 (JAX x64-disabled truncates the requested int64).
// CSR build forked onto a side stream, overlapped with GEMM1.
// ---------------------------------------------------------------------------

#define NMAX 50000
#define EMAX 800000
typedef unsigned long long ull;

__device__ int   g_indeg [NMAX];
__device__ int   g_cursor[NMAX];
__device__ int   g_rowptr[NMAX + 1];
__device__ int   g_scan  [NMAX];
__device__ int   g_bsum  [256];
__device__ int   g_boff  [256];
__device__ float g_dinv  [NMAX];
__device__ __align__(16) ull   g_emeta[EMAX];        // hi: norm bits, lo: src
__device__ __align__(16) float g_h1   [NMAX * 128];
__device__ __align__(16) float g_h2   [NMAX * 16];
__device__ __align__(16) __nv_bfloat16 g_W1h[256 * 128];
__device__ __align__(16) __nv_bfloat16 g_W1l[256 * 128];

// ---------------- helpers ---------------------------------------------------

__device__ __forceinline__ ull pack2f(float lo, float hi) {
    ull d;
    asm("mov.b64 %0, {%1, %2};" : "=l"(d) : "r"(__float_as_uint(lo)), "r"(__float_as_uint(hi)));
    return d;
}
__device__ __forceinline__ void ldm_x4(unsigned& r0, unsigned& r1, unsigned& r2, unsigned& r3,
                                       unsigned addr) {
    asm volatile("ldmatrix.sync.aligned.m8n8.x4.shared.b16 {%0,%1,%2,%3}, [%4];"
                 : "=r"(r0), "=r"(r1), "=r"(r2), "=r"(r3) : "r"(addr));
}
__device__ __forceinline__ void ldm_x4t(unsigned& r0, unsigned& r1, unsigned& r2, unsigned& r3,
                                        unsigned addr) {
    asm volatile("ldmatrix.sync.aligned.m8n8.x4.trans.shared.b16 {%0,%1,%2,%3}, [%4];"
                 : "=r"(r0), "=r"(r1), "=r"(r2), "=r"(r3) : "r"(addr));
}
__device__ __forceinline__ void mma_bf16(float* c, const unsigned* a, unsigned b0, unsigned b1) {
    asm volatile("mma.sync.aligned.m16n8k16.row.col.f32.bf16.bf16.f32 "
                 "{%0,%1,%2,%3}, {%4,%5,%6,%7}, {%8,%9}, {%0,%1,%2,%3};"
                 : "+f"(c[0]), "+f"(c[1]), "+f"(c[2]), "+f"(c[3])
                 : "r"(a[0]), "r"(a[1]), "r"(a[2]), "r"(a[3]), "r"(b0), "r"(b1));
}

// ---------------- CSR build ------------------------------------------------

__global__ void k_init(int n) {
    int i = blockIdx.x * blockDim.x + threadIdx.x;
    if (i < n) { g_indeg[i] = 0; g_cursor[i] = 0; }
}

__global__ void k_deg_count(const int* __restrict__ dst, int E) {
    int e = blockIdx.x * blockDim.x + threadIdx.x;
    if (e < E) atomicAdd(&g_indeg[dst[e]], 1);
}

__global__ void k_scan1(int n) {
    __shared__ int wsum[8];
    int t = threadIdx.x, i = blockIdx.x * 256 + t;
    int lane = t & 31, w = t >> 5;
    int x = (i < n) ? g_indeg[i] : 0;
#pragma unroll
    for (int o = 1; o < 32; o <<= 1) {
        int y = __shfl_up_sync(0xffffffffu, x, o);
        if (lane >= o) x += y;
    }
    if (lane == 31) wsum[w] = x;
    __syncthreads();
    if (w == 0) {
        int s = (lane < 8) ? wsum[lane] : 0;
#pragma unroll
        for (int o = 1; o < 8; o <<= 1) {
            int y = __shfl_up_sync(0xffffffffu, s, o);
            if (lane >= o) s += y;
        }
        if (lane < 8) wsum[lane] = s;
    }
    __syncthreads();
    if (w > 0) x += wsum[w - 1];
    if (i < n) g_scan[i] = x;
    if (t == 255) g_bsum[blockIdx.x] = x;
}

__global__ void k_scan2(int nb) {
    __shared__ int wsum[8];
    int t = threadIdx.x;
    int lane = t & 31, w = t >> 5;
    int v = (t < nb) ? g_bsum[t] : 0;
    int x = v;
#pragma unroll
    for (int o = 1; o < 32; o <<= 1) {
        int y = __shfl_up_sync(0xffffffffu, x, o);
        if (lane >= o) x += y;
    }
    if (lane == 31) wsum[w] = x;
    __syncthreads();
    if (w == 0) {
        int s = (lane < 8) ? wsum[lane] : 0;
#pragma unroll
        for (int o = 1; o < 8; o <<= 1) {
            int y = __shfl_up_sync(0xffffffffu, s, o);
            if (lane >= o) s += y;
        }
        if (lane < 8) wsum[lane] = s;
    }
    __syncthreads();
    if (w > 0) x += wsum[w - 1];
    g_boff[t] = x - v;   // exclusive
}

__global__ void k_scan3(int n) {     // rowptr + dinv
    int i = blockIdx.x * blockDim.x + threadIdx.x;
    if (i >= n) return;
    int deg = g_indeg[i];
    int off = g_boff[i >> 8];
    g_rowptr[i] = g_scan[i] - deg + off;
    if (i == n - 1) g_rowptr[n] = g_scan[i] + off;
    g_dinv[i] = rsqrtf((float)(deg + 1));
}

__global__ void k_fill(const int* __restrict__ src, const int* __restrict__ dst, int E) {
    int e = blockIdx.x * blockDim.x + threadIdx.x;
    if (e >= E) return;
    int s = src[e], d = dst[e];
    int pos = g_rowptr[d] + atomicAdd(&g_cursor[d], 1);
    float nm = g_dinv[s] * g_dinv[d];
    g_emeta[pos] = ((ull)__float_as_uint(nm) << 32) | (unsigned)s;
}

// ---------------- W1 bf16 hi/lo pre-split (once) ---------------------------

__global__ void k_convW(const float* __restrict__ W) {
    int i = blockIdx.x * blockDim.x + threadIdx.x;
    if (i >= 256 * 128) return;
    float w = W[i];
    __nv_bfloat16 h = __float2bfloat16(w);
    g_W1h[i] = h;
    g_W1l[i] = __float2bfloat16(w - __bfloat162float(h));
}

// ---------------- GEMM1 via mma.sync: h1 = x @ W1 --------------------------
// 128x128 tile, 256 thr (8 warps: 4 m-warps x 2 n-warps), K-chunks of 32.
// x = hi+lo bf16 split (A, converted in-kernel), W pre-split (pure copy).
// D += AhBh + AhBl + AlBh.
// A smem [128][40] bf16; B smem [32][136] bf16 k-major (ldmatrix.trans).

#define A_PITCH 40
#define B_PITCH 136

__global__ void __launch_bounds__(256, 2) k_gemm1(const float* __restrict__ X, int n) {
    __shared__ __align__(16) __nv_bfloat16 Ah[128][A_PITCH];
    __shared__ __align__(16) __nv_bfloat16 Al[128][A_PITCH];
    __shared__ __align__(16) __nv_bfloat16 Bh[32][B_PITCH];
    __shared__ __align__(16) __nv_bfloat16 Bl[32][B_PITCH];

    const int tid  = threadIdx.x;
    const int wid  = tid >> 5;
    const int lane = tid & 31;
    const int wm   = wid & 3;          // m-warp: rows wm*32..+31
    const int wn   = wid >> 2;         // n-warp: cols wn*64..+63
    const int row0 = blockIdx.x * 128;

    float acc[2][8][4];                // [mtile][n8tile][frag]
#pragma unroll
    for (int mt = 0; mt < 2; mt++)
#pragma unroll
        for (int nt = 0; nt < 8; nt++)
#pragma unroll
            for (int q = 0; q < 4; q++) acc[mt][nt][q] = 0.f;

    for (int ch = 0; ch < 8; ch++) {
        const int k0 = ch << 5;
        // ---- stage A (X): 128 rows x 32 k, bf16 hi/lo (convert here) ----
#pragma unroll
        for (int i = tid; i < 1024; i += 256) {
            int r = i >> 3, f4 = i & 7;
            int gr = row0 + r;
            float4 v = make_float4(0.f, 0.f, 0.f, 0.f);
            if (gr < n) v = *(const float4*)(X + (size_t)gr * 256 + k0 + (f4 << 2));
            float xs[4] = {v.x, v.y, v.z, v.w};
            unsigned hw0, hw1, lw0, lw1;
            {
                __nv_bfloat16 h0 = __float2bfloat16(xs[0]);
                __nv_bfloat16 h1b = __float2bfloat16(xs[1]);
                __nv_bfloat16 l0 = __float2bfloat16(xs[0] - __bfloat162float(h0));
                __nv_bfloat16 l1 = __float2bfloat16(xs[1] - __bfloat162float(h1b));
                hw0 = (unsigned)__bfloat16_as_ushort(h0) | ((unsigned)__bfloat16_as_ushort(h1b) << 16);
                lw0 = (unsigned)__bfloat16_as_ushort(l0) | ((unsigned)__bfloat16_as_ushort(l1) << 16);
            }
            {
                __nv_bfloat16 h0 = __float2bfloat16(xs[2]);
                __nv_bfloat16 h1b = __float2bfloat16(xs[3]);
                __nv_bfloat16 l0 = __float2bfloat16(xs[2] - __bfloat162float(h0));
                __nv_bfloat16 l1 = __float2bfloat16(xs[3] - __bfloat162float(h1b));
                hw1 = (unsigned)__bfloat16_as_ushort(h0) | ((unsigned)__bfloat16_as_ushort(h1b) << 16);
                lw1 = (unsigned)__bfloat16_as_ushort(l0) | ((unsigned)__bfloat16_as_ushort(l1) << 16);
            }
            *(ull*)&Ah[r][f4 << 2] = ((ull)hw1 << 32) | hw0;
            *(ull*)&Al[r][f4 << 2] = ((ull)lw1 << 32) | lw0;
        }
        // ---- stage B (W): pure bf16 copy from pre-split globals ----
#pragma unroll
        for (int i = tid; i < 1024; i += 256) {
            int kk = i >> 5, n0 = (i & 31) << 2;
            const int gidx = (k0 + kk) * 128 + n0;
            *(ull*)&Bh[kk][n0] = *(const ull*)(g_W1h + gidx);
            *(ull*)&Bl[kk][n0] = *(const ull*)(g_W1l + gidx);
        }
        __syncthreads();

#pragma unroll
        for (int ks = 0; ks < 32; ks += 16) {
            unsigned aH[2][4], aL[2][4];
#pragma unroll
            for (int mt = 0; mt < 2; mt++) {
                int ar = wm * 32 + mt * 16 + (lane & 15);
                int ac = ks + ((lane >> 4) << 3);
                unsigned addrH = (unsigned)__cvta_generic_to_shared(&Ah[ar][ac]);
                unsigned addrL = (unsigned)__cvta_generic_to_shared(&Al[ar][ac]);
                ldm_x4(aH[mt][0], aH[mt][1], aH[mt][2], aH[mt][3], addrH);
                ldm_x4(aL[mt][0], aL[mt][1], aL[mt][2], aL[mt][3], addrL);
            }
#pragma unroll
            for (int ng = 0; ng < 4; ng++) {
                int nb0 = wn * 64 + ng * 16;
                int br = ks + (lane & 15);
                int bc = nb0 + ((lane >> 4) << 3);
                unsigned addrH = (unsigned)__cvta_generic_to_shared(&Bh[br][bc]);
                unsigned addrL = (unsigned)__cvta_generic_to_shared(&Bl[br][bc]);
                unsigned bh[4], bl[4];
                ldm_x4t(bh[0], bh[1], bh[2], bh[3], addrH);
                ldm_x4t(bl[0], bl[1], bl[2], bl[3], addrL);
#pragma unroll
                for (int mt = 0; mt < 2; mt++) {
#pragma unroll
                    for (int nt = 0; nt < 2; nt++) {
                        float* c = acc[mt][ng * 2 + nt];
                        mma_bf16(c, aH[mt], bh[nt * 2], bh[nt * 2 + 1]);   // hi*hi
                        mma_bf16(c, aH[mt], bl[nt * 2], bl[nt * 2 + 1]);   // hi*lo
                        mma_bf16(c, aL[mt], bh[nt * 2], bh[nt * 2 + 1]);   // lo*hi
                    }
                }
            }
        }
        __syncthreads();
    }

    // ---- epilogue ----
#pragma unroll
    for (int mt = 0; mt < 2; mt++) {
#pragma unroll
        for (int nt = 0; nt < 8; nt++) {
            int col = wn * 64 + nt * 8 + ((lane & 3) << 1);
            int r0  = row0 + wm * 32 + mt * 16 + (lane >> 2);
            if (r0 < n)
                *(ull*)(g_h1 + (size_t)r0 * 128 + col) = pack2f(acc[mt][nt][0], acc[mt][nt][1]);
            if (r0 + 8 < n)
                *(ull*)(g_h1 + (size_t)(r0 + 8) * 128 + col) = pack2f(acc[mt][nt][2], acc[mt][nt][3]);
        }
    }
}

// ---------------- fused gather1 + GEMM2 (warp per node) --------------------

__global__ void __launch_bounds__(256) k_gather1_gemm2(const float* __restrict__ b1,
                                                       const float* __restrict__ W2,
                                                       int n) {
    __shared__ float W2s[16][132];
    __shared__ float hidS[8][128];
    const int tid  = threadIdx.x;
    const int w    = tid >> 5;
    const int lane = tid & 31;

#pragma unroll
    for (int i = tid; i < 2048; i += 256) {
        int k = i >> 4, j = i & 15;
        W2s[j][k] = W2[k * 16 + j];
    }
    __syncthreads();

    int node = blockIdx.x * 8 + w;
    if (node >= n) return;
    int c = lane << 2;

    float di  = g_dinv[node];
    float di2 = di * di;
    float4 h  = *(const float4*)(g_h1 + (size_t)node * 128 + c);
    float4 a;
    a.x = di2 * h.x; a.y = di2 * h.y; a.z = di2 * h.z; a.w = di2 * h.w;

    int beg = g_rowptr[node], end = g_rowptr[node + 1];
    if (beg < end) {
        ull m0 = g_emeta[beg];
        float4 v0 = *(const float4*)(g_h1 + (size_t)(unsigned)m0 * 128 + c);
        for (int e = beg + 1; e < end; e++) {
            ull m1 = g_emeta[e];
            float4 v1 = *(const float4*)(g_h1 + (size_t)(unsigned)m1 * 128 + c);
            float nm = __uint_as_float((unsigned)(m0 >> 32));
            a.x += nm * v0.x; a.y += nm * v0.y; a.z += nm * v0.z; a.w += nm * v0.w;
            m0 = m1; v0 = v1;
        }
        float nm = __uint_as_float((unsigned)(m0 >> 32));
        a.x += nm * v0.x; a.y += nm * v0.y; a.z += nm * v0.z; a.w += nm * v0.w;
    }
    float4 b = *(const float4*)(b1 + c);
    float4 o;
    o.x = fmaxf(a.x + b.x, 0.f);
    o.y = fmaxf(a.y + b.y, 0.f);
    o.z = fmaxf(a.z + b.z, 0.f);
    o.w = fmaxf(a.w + b.w, 0.f);

    *(float4*)&hidS[w][c] = o;
    __syncwarp();

    const int j  = lane & 15;
    const int k0 = (lane >> 4) << 6;
    float acc = 0.f;
#pragma unroll
    for (int kk = 0; kk < 64; kk += 4) {
        float4 hv = *(float4*)&hidS[w][k0 + kk];
        float4 wv = *(float4*)&W2s[j][k0 + kk];
        acc += hv.x * wv.x + hv.y * wv.y + hv.z * wv.z + hv.w * wv.w;
    }
    acc += __shfl_down_sync(0xffffffffu, acc, 16);
    if (lane < 16) g_h2[(size_t)node * 16 + j] = acc;
}

// ---------------- gather layer 2 + log_softmax (4 lanes per node) ----------

__global__ void __launch_bounds__(256) k_gather2(const float* __restrict__ b2,
                                                 float* __restrict__ out, int n) {
    int g    = blockIdx.x * 256 + threadIdx.x;
    int node = g >> 2, q = g & 3;
    if (node >= n) return;
    int c = q << 2;

    float di  = g_dinv[node];
    float di2 = di * di;
    float4 h  = *(const float4*)(g_h2 + (size_t)node * 16 + c);
    float4 a;
    a.x = di2 * h.x; a.y = di2 * h.y; a.z = di2 * h.z; a.w = di2 * h.w;

    int beg = g_rowptr[node], end = g_rowptr[node + 1];
    if (beg < end) {
        ull m0 = g_emeta[beg];
        float4 v0 = *(const float4*)(g_h2 + (size_t)(unsigned)m0 * 16 + c);
        for (int e = beg + 1; e < end; e++) {
            ull m1 = g_emeta[e];
            float4 v1 = *(const float4*)(g_h2 + (size_t)(unsigned)m1 * 16 + c);
            float nm = __uint_as_float((unsigned)(m0 >> 32));
            a.x += nm * v0.x; a.y += nm * v0.y; a.z += nm * v0.z; a.w += nm * v0.w;
            m0 = m1; v0 = v1;
        }
        float nm = __uint_as_float((unsigned)(m0 >> 32));
        a.x += nm * v0.x; a.y += nm * v0.y; a.z += nm * v0.z; a.w += nm * v0.w;
    }
    float4 b = *(const float4*)(b2 + c);
    a.x += b.x; a.y += b.y; a.z += b.z; a.w += b.w;

    float m4 = fmaxf(fmaxf(a.x, a.y), fmaxf(a.z, a.w));
    m4 = fmaxf(m4, __shfl_xor_sync(0xffffffffu, m4, 1, 4));
    m4 = fmaxf(m4, __shfl_xor_sync(0xffffffffu, m4, 2, 4));
    float s4 = expf(a.x - m4) + expf(a.y - m4) + expf(a.z - m4) + expf(a.w - m4);
    s4 += __shfl_xor_sync(0xffffffffu, s4, 1, 4);
    s4 += __shfl_xor_sync(0xffffffffu, s4, 2, 4);
    float lse = m4 + logf(s4);

    float4 o;
    o.x = a.x - lse; o.y = a.y - lse; o.z = a.z - lse; o.w = a.w - lse;
    *(float4*)(out + (size_t)node * 16 + c) = o;
}

// ---------------------------------------------------------------------------

extern "C" void kernel_launch(void* const* d_in, const int* in_sizes, int n_in,
                              void* d_out, int out_size) {
    const float* x  = (const float*)d_in[0];
    const int*   ei = (const int*)d_in[1];          // int32 (JAX truncation)
    const float* W1 = (const float*)d_in[2];
    const float* b1 = (const float*)d_in[3];
    const float* W2 = (const float*)d_in[4];
    const float* b2 = (const float*)d_in[5];
    float*       out = (float*)d_out;

    const int n = in_sizes[0] / 256;
    const int E = in_sizes[1] / 2;
    const int* src = ei;
    const int* dst = ei + E;
    const int nb = (n + 255) / 256;

    const int T = 256;
    dim3 b(T);

    static cudaStream_t sCsr = nullptr;
    static cudaEvent_t  eFork = nullptr, eJoin = nullptr;
    if (!sCsr) {
        cudaStreamCreateWithFlags(&sCsr, cudaStreamNonBlocking);
        cudaEventCreateWithFlags(&eFork, cudaEventDisableTiming);
        cudaEventCreateWithFlags(&eJoin, cudaEventDisableTiming);
    }

    // fork: CSR build on side stream, W-split + GEMM1 on main stream
    cudaEventRecord(eFork, 0);
    cudaStreamWaitEvent(sCsr, eFork, 0);

    k_convW    <<<128, b>>>(W1);                          // main, ~2us
    k_init     <<<(n + T - 1) / T, b, 0, sCsr>>>(n);
    k_deg_count<<<(E + T - 1) / T, b, 0, sCsr>>>(dst, E);

    k_gemm1<<<(n + 127) / 128, b>>>(x, n);                // 4th launch (ncu window)

    k_scan1    <<<nb, b, 0, sCsr>>>(n);
    k_scan2    <<<1, b, 0, sCsr>>>(nb);
    k_scan3    <<<nb, b, 0, sCsr>>>(n);
    k_fill     <<<(E + T - 1) / T, b, 0, sCsr>>>(src, dst, E);
    cudaEventRecord(eJoin, sCsr);

    // join, then the dependent chain
    cudaStreamWaitEvent(0, eJoin, 0);
    k_gather1_gemm2<<<(n + 7) / 8, b>>>(b1, W2, n);
    k_gather2<<<(n * 4 + T - 1) / T, b>>>(b2, out, n);
}